// round 1
// baseline (speedup 1.0000x reference)
#include <cuda_runtime.h>
#include <math.h>
#include <stdint.h>

// Problem constants
#define BB   4
#define NSEQ 4096
#define EE   1024
#define HH   16
#define DD   64
#define MM   256
#define TT   (BB*NSEQ)     // 16384
#define BHn  (BB*HH)       // 64
#define NSEG 16            // split-K segments for context

// ---------------- device scratch (no allocation allowed) ----------------
__device__ float g_q[(size_t)BHn*NSEQ*DD];        // 64 MB, [bh, n, d]
__device__ float g_k[(size_t)BHn*NSEQ*DD];        // 64 MB
__device__ float g_v[(size_t)BHn*NSEQ*DD];        // 64 MB
__device__ float g_qf[(size_t)BHn*NSEQ*MM];       // 256 MB, [bh, n, m]
__device__ float g_kf[(size_t)BHn*NSEQ*MM];       // 256 MB (pass1: raw dd, pass2: kf)
__device__ float g_diagk[BHn*NSEQ];               // per-row diag for k
__device__ float g_ksum[BHn*MM];                  // [bh, m]
__device__ float g_ctxp[(size_t)NSEG*BHn*MM*DD];  // split-K partials, 64 MB
__device__ float g_ctx[BHn*MM*DD];                // [bh, m, d], 4 MB
__device__ float g_attn[(size_t)TT*EE];           // 64 MB, [b, n, e]
__device__ float g_kstab;                         // global max of dd_k

// ---------------- helpers ----------------
__device__ __forceinline__ void atomicMaxFloat(float* addr, float v) {
    if (v >= 0.f) atomicMax((int*)addr, __float_as_int(v));
    else          atomicMin((unsigned int*)addr, __float_as_uint(v));
}

__global__ void init_kernel() {
    if (blockIdx.x == 0 && threadIdx.x == 0) g_kstab = -INFINITY;
}

// ---------------- generic fp32 GEMM:  C = A[Mr,K] * B[Nc,K]^T + bias ----------------
// OUT_MODE 0: C row-major [Mr, Nc]
// OUT_MODE 1: head-split: row t=(b,n), col e=(h,d) -> C[((b*H+h)*N+n)*D+d]
template<int OUT_MODE>
__global__ __launch_bounds__(256) void sgemm_nt(
    const float* __restrict__ A, const float* __restrict__ Bw,
    const float* __restrict__ bias, float* __restrict__ C,
    int Mr, int Nc, int K)
{
    __shared__ float sA[16][128];
    __shared__ float sB[16][128];
    const int tid = threadIdx.x;
    const int bm = blockIdx.y * 128;
    const int bn = blockIdx.x * 128;
    const int ty = tid >> 4;
    const int tx = tid & 15;

    float acc[8][8];
#pragma unroll
    for (int i = 0; i < 8; i++)
#pragma unroll
        for (int j = 0; j < 8; j++) acc[i][j] = 0.f;

    for (int k0 = 0; k0 < K; k0 += 16) {
#pragma unroll
        for (int i = 0; i < 2; i++) {
            int f  = tid * 2 + i;          // 0..511
            int r  = f >> 2;               // 0..127
            int kq = (f & 3) * 4;          // 0,4,8,12
            float4 va = *(const float4*)(A  + (size_t)(bm + r) * K + k0 + kq);
            sA[kq + 0][r] = va.x; sA[kq + 1][r] = va.y;
            sA[kq + 2][r] = va.z; sA[kq + 3][r] = va.w;
            float4 vb = *(const float4*)(Bw + (size_t)(bn + r) * K + k0 + kq);
            sB[kq + 0][r] = vb.x; sB[kq + 1][r] = vb.y;
            sB[kq + 2][r] = vb.z; sB[kq + 3][r] = vb.w;
        }
        __syncthreads();
#pragma unroll
        for (int kk = 0; kk < 16; kk++) {
            float a[8], b[8];
            *(float4*)(a)     = *(const float4*)(&sA[kk][ty * 8]);
            *(float4*)(a + 4) = *(const float4*)(&sA[kk][ty * 8 + 4]);
            *(float4*)(b)     = *(const float4*)(&sB[kk][tx * 8]);
            *(float4*)(b + 4) = *(const float4*)(&sB[kk][tx * 8 + 4]);
#pragma unroll
            for (int i = 0; i < 8; i++)
#pragma unroll
                for (int j = 0; j < 8; j++)
                    acc[i][j] += a[i] * b[j];
        }
        __syncthreads();
    }

#pragma unroll
    for (int i = 0; i < 8; i++) {
        int row = bm + ty * 8 + i;
#pragma unroll
        for (int j = 0; j < 8; j++) {
            int col = bn + tx * 8 + j;
            float v = acc[i][j] + bias[col];
            if (OUT_MODE == 0) {
                C[(size_t)row * Nc + col] = v;
            } else {
                int b_ = row / NSEQ, n_ = row % NSEQ;
                int h_ = col / DD,  d_ = col % DD;
                C[(((size_t)(b_ * HH + h_)) * NSEQ + n_) * DD + d_] = v;
            }
        }
    }
}

// ---------------- FAVOR+ feature kernel ----------------
// Block: 32 rows of one head, all M=256 features. dd = (x * 64^-0.25) @ proj^T.
// is_query: qf = ratio*(exp(dd - diag - rowmax) + eps)
// else:     write raw dd to F, diag to diag_out, atomicMax block max into g_kstab
__global__ __launch_bounds__(256) void feat_kernel(
    const float* __restrict__ X,    // [BH, N, D]
    const float* __restrict__ proj, // [M, D]
    float* __restrict__ F,          // [BH, N, M]
    float* __restrict__ diag_out,
    int is_query)
{
    extern __shared__ float sm[];
    float* sPT = sm;                // [D][M] transposed proj (64*256)
    float* sX  = sm + DD * MM;      // [32][D]
    __shared__ float s_wmax[8];

    const int tid = threadIdx.x;
    const int bh  = blockIdx.x;
    const int n0  = blockIdx.y * 32;

    // load proj transposed: thread tid owns proj row m=tid (conflict-free smem stores)
    {
        const float4* pr = (const float4*)(proj + tid * DD);
#pragma unroll
        for (int t = 0; t < 16; t++) {
            float4 v = pr[t];
            int d = t * 4;
            sPT[(d + 0) * MM + tid] = v.x;
            sPT[(d + 1) * MM + tid] = v.y;
            sPT[(d + 2) * MM + tid] = v.z;
            sPT[(d + 3) * MM + tid] = v.w;
        }
    }
    // load + scale 32x64 data tile
    {
        const float SC = 0.3535533905932738f;  // 64^-0.25
        const float4* xr = (const float4*)(X + ((size_t)bh * NSEQ + n0) * DD);
        float4* sx4 = (float4*)sX;
#pragma unroll
        for (int i = 0; i < 2; i++) {
            int f = tid * 2 + i;               // 0..511
            float4 v = xr[f];
            sx4[f] = make_float4(v.x * SC, v.y * SC, v.z * SC, v.w * SC);
        }
    }
    __syncthreads();

    const int lane = tid & 31;
    const int w    = tid >> 5;    // warp 0..7 -> rows w*4..w*4+3
    const int m0   = lane * 8;

    float acc[4][8];
#pragma unroll
    for (int r = 0; r < 4; r++)
#pragma unroll
        for (int j = 0; j < 8; j++) acc[r][j] = 0.f;

#pragma unroll 16
    for (int d = 0; d < DD; d++) {
        float b[8];
        *(float4*)(b)     = *(const float4*)(&sPT[d * MM + m0]);
        *(float4*)(b + 4) = *(const float4*)(&sPT[d * MM + m0 + 4]);
#pragma unroll
        for (int r = 0; r < 4; r++) {
            float a = sX[(w * 4 + r) * DD + d];
#pragma unroll
            for (int j = 0; j < 8; j++) acc[r][j] += a * b[j];
        }
    }

    // per-row diag = 0.5 * sum(x^2): 2 d-elements per lane + warp reduce
    float dg[4];
#pragma unroll
    for (int r = 0; r < 4; r++) {
        const float* xr = &sX[(w * 4 + r) * DD];
        float x0 = xr[lane * 2], x1 = xr[lane * 2 + 1];
        float p = x0 * x0 + x1 * x1;
#pragma unroll
        for (int o = 16; o > 0; o >>= 1) p += __shfl_xor_sync(0xffffffffu, p, o);
        dg[r] = 0.5f * p;
    }

    const float RATIO = 0.0625f;   // M^-0.5
    const float EPSK  = 1e-4f;

    if (is_query) {
#pragma unroll
        for (int r = 0; r < 4; r++) {
            float mx = acc[r][0];
#pragma unroll
            for (int j = 1; j < 8; j++) mx = fmaxf(mx, acc[r][j]);
#pragma unroll
            for (int o = 16; o > 0; o >>= 1)
                mx = fmaxf(mx, __shfl_xor_sync(0xffffffffu, mx, o));
            float sub = dg[r] + mx;
            float o8[8];
#pragma unroll
            for (int j = 0; j < 8; j++)
                o8[j] = RATIO * (expf(acc[r][j] - sub) + EPSK);
            float4* dst = (float4*)(F + ((size_t)bh * NSEQ + n0 + w * 4 + r) * MM + m0);
            dst[0] = *(float4*)(o8);
            dst[1] = *(float4*)(o8 + 4);
        }
    } else {
        float wmx = -INFINITY;
#pragma unroll
        for (int r = 0; r < 4; r++) {
            float4* dst = (float4*)(F + ((size_t)bh * NSEQ + n0 + w * 4 + r) * MM + m0);
            dst[0] = *(float4*)(&acc[r][0]);
            dst[1] = *(float4*)(&acc[r][4]);
#pragma unroll
            for (int j = 0; j < 8; j++) wmx = fmaxf(wmx, acc[r][j]);
        }
        if (lane == 0) {
#pragma unroll
            for (int r = 0; r < 4; r++)
                diag_out[bh * NSEQ + n0 + w * 4 + r] = dg[r];
        }
#pragma unroll
        for (int o = 16; o > 0; o >>= 1)
            wmx = fmaxf(wmx, __shfl_xor_sync(0xffffffffu, wmx, o));
        if (lane == 0) s_wmax[w] = wmx;
        __syncthreads();
        if (tid == 0) {
            float m = s_wmax[0];
#pragma unroll
            for (int i = 1; i < 8; i++) m = fmaxf(m, s_wmax[i]);
            atomicMaxFloat(&g_kstab, m);
        }
    }
}

// ---------------- key features pass 2: apply exp with global stab ----------------
__global__ __launch_bounds__(256) void kpass2_kernel() {
    const float RATIO = 0.0625f;
    const float EPSK  = 1e-4f;
    const float stab  = g_kstab;
    const size_t total4 = (size_t)BHn * NSEQ * MM / 4;
    float4* kf4 = (float4*)g_kf;
    for (size_t i = (size_t)blockIdx.x * blockDim.x + threadIdx.x; i < total4;
         i += (size_t)gridDim.x * blockDim.x) {
        size_t row = (i * 4) / MM;   // bh*N + n (M%4==0, no row split)
        float sub = g_diagk[row] + stab;
        float4 v = kf4[i];
        v.x = RATIO * (expf(v.x - sub) + EPSK);
        v.y = RATIO * (expf(v.y - sub) + EPSK);
        v.z = RATIO * (expf(v.z - sub) + EPSK);
        v.w = RATIO * (expf(v.w - sub) + EPSK);
        kf4[i] = v;
    }
}

// ---------------- k_sum[bh,m] = sum_n kf[bh,n,m] (deterministic, per-head block) ----------------
__global__ __launch_bounds__(256) void ksum_kernel() {
    int bh = blockIdx.x;
    int m  = threadIdx.x;
    const float* base = g_kf + (size_t)bh * NSEQ * MM + m;
    float s = 0.f;
#pragma unroll 8
    for (int n = 0; n < NSEQ; n++) s += base[(size_t)n * MM];
    g_ksum[bh * MM + m] = s;
}

// ---------------- context partials: ctxp[seg][bh][m][d] = sum_{n in seg} kf[n,m]*v[n,d] ----------------
__global__ __launch_bounds__(256) void ctx_kernel() {
    __shared__ float  sK[16][MM];
    __shared__ float4 sV[16][16];   // 16 n-rows x 64 d
    const int bh  = blockIdx.x;
    const int seg = blockIdx.y;
    const int tid = threadIdx.x;
    const int tx  = tid & 15;       // d group: d0 = tx*4
    const int ty  = tid >> 4;       // m group: m0 = ty*16

    float4 acc[16];
#pragma unroll
    for (int i = 0; i < 16; i++) acc[i] = make_float4(0.f, 0.f, 0.f, 0.f);

    const int nbase = seg * (NSEQ / NSEG);
    for (int n0 = nbase; n0 < nbase + NSEQ / NSEG; n0 += 16) {
        const float* kb = g_kf + ((size_t)bh * NSEQ + n0) * MM;
#pragma unroll
        for (int t = 0; t < 16; t++) {
            int idx = tid + t * 256;               // 0..4095
            sK[idx >> 8][idx & 255] = kb[idx];
        }
        const float* vb = g_v + ((size_t)bh * NSEQ + n0) * DD;
        float* sVf = (float*)sV;
#pragma unroll
        for (int t = 0; t < 4; t++) {
            int idx = tid + t * 256;               // 0..1023
            sVf[idx] = vb[idx];
        }
        __syncthreads();
#pragma unroll
        for (int r = 0; r < 16; r++) {
            float4 bv = sV[r][tx];
#pragma unroll
            for (int i = 0; i < 16; i++) {
                float a = sK[r][ty * 16 + i];
                acc[i].x += a * bv.x; acc[i].y += a * bv.y;
                acc[i].z += a * bv.z; acc[i].w += a * bv.w;
            }
        }
        __syncthreads();
    }
    float4* cp = (float4*)(g_ctxp + ((size_t)seg * BHn + bh) * MM * DD);
#pragma unroll
    for (int i = 0; i < 16; i++) {
        int m = ty * 16 + i;
        cp[(m * DD) / 4 + tx] = acc[i];
    }
}

__global__ __launch_bounds__(256) void ctx_reduce_kernel() {
    int i = blockIdx.x * 256 + threadIdx.x;   // BH*M*D = 1,048,576
    if (i < BHn * MM * DD) {
        float s = 0.f;
#pragma unroll
        for (int seg = 0; seg < NSEG; seg++)
            s += g_ctxp[(size_t)seg * BHn * MM * DD + i];
        g_ctx[i] = s;
    }
}

// ---------------- out = d_inv * (qf @ ctx), written back as [b,n,h*D+d] ----------------
__global__ __launch_bounds__(256) void attn_kernel() {
    extern __shared__ float sm[];
    float* sCtx = sm;                  // [M][D]  (64 KB)
    float* sQF  = sm + MM * DD;        // [32][M] (32 KB)
    float* sKs  = sQF + 32 * MM;       // [M]
    const int bh = blockIdx.x;
    const int b  = bh >> 4;
    const int h  = bh & 15;
    const int n0 = blockIdx.y * 32;
    const int tid  = threadIdx.x;
    const int lane = tid & 31;
    const int w    = tid >> 5;

    const float* cb = g_ctx + (size_t)bh * MM * DD;
#pragma unroll
    for (int t = 0; t < 64; t++) sCtx[tid + t * 256] = cb[tid + t * 256];
    const float* qb = g_qf + ((size_t)bh * NSEQ + n0) * MM;
#pragma unroll
    for (int t = 0; t < 32; t++) sQF[tid + t * 256] = qb[tid + t * 256];
    sKs[tid] = g_ksum[bh * MM + tid];
    __syncthreads();

    const float2* sCtx2 = (const float2*)sCtx;   // [m*32 + d/2]
#pragma unroll
    for (int r4 = 0; r4 < 4; r4++) {
        int r = w * 4 + r4;
        const float* q = &sQF[r * MM];
        float ax = 0.f, ay = 0.f, dp = 0.f;
#pragma unroll 8
        for (int m = 0; m < MM; m++) {
            float qv = q[m];
            dp += qv * sKs[m];
            float2 c = sCtx2[m * 32 + lane];
            ax += qv * c.x; ay += qv * c.y;
        }
        float dinv = 1.f / dp;
        float2* outp = (float2*)(g_attn + ((size_t)(b * NSEQ + n0 + r)) * EE + h * DD);
        outp[lane] = make_float2(ax * dinv, ay * dinv);
    }
}

// ---------------- launch ----------------
extern "C" void kernel_launch(void* const* d_in, const int* in_sizes, int n_in,
                              void* d_out, int out_size) {
    const float* x    = (const float*)d_in[0];
    const float* Wq   = (const float*)d_in[1];
    const float* bq   = (const float*)d_in[2];
    const float* Wk   = (const float*)d_in[3];
    const float* bk   = (const float*)d_in[4];
    const float* Wv   = (const float*)d_in[5];
    const float* bv   = (const float*)d_in[6];
    const float* Wo   = (const float*)d_in[7];
    const float* bo   = (const float*)d_in[8];
    const float* proj = (const float*)d_in[9];
    float* out = (float*)d_out;

    float *pq, *pk, *pv, *pqf, *pkf, *pdg, *pattn;
    cudaGetSymbolAddress((void**)&pq,    g_q);
    cudaGetSymbolAddress((void**)&pk,    g_k);
    cudaGetSymbolAddress((void**)&pv,    g_v);
    cudaGetSymbolAddress((void**)&pqf,   g_qf);
    cudaGetSymbolAddress((void**)&pkf,   g_kf);
    cudaGetSymbolAddress((void**)&pdg,   g_diagk);
    cudaGetSymbolAddress((void**)&pattn, g_attn);

    const int FEAT_SMEM = (DD * MM + 32 * DD) * (int)sizeof(float);            // 73728
    const int ATTN_SMEM = (MM * DD + 32 * MM + MM) * (int)sizeof(float);       // 99328
    cudaFuncSetAttribute(feat_kernel, cudaFuncAttributeMaxDynamicSharedMemorySize, FEAT_SMEM);
    cudaFuncSetAttribute(attn_kernel, cudaFuncAttributeMaxDynamicSharedMemorySize, ATTN_SMEM);

    init_kernel<<<1, 32>>>();

    dim3 gg(EE / 128, TT / 128);     // 8 x 128 blocks
    sgemm_nt<1><<<gg, 256>>>(x, Wq, bq, pq, TT, EE, EE);
    sgemm_nt<1><<<gg, 256>>>(x, Wk, bk, pk, TT, EE, EE);
    sgemm_nt<1><<<gg, 256>>>(x, Wv, bv, pv, TT, EE, EE);

    dim3 gf(BHn, NSEQ / 32);         // 64 x 128
    feat_kernel<<<gf, 256, FEAT_SMEM>>>(pq, proj, pqf, nullptr, 1);
    feat_kernel<<<gf, 256, FEAT_SMEM>>>(pk, proj, pkf, pdg, 0);

    kpass2_kernel<<<8192, 256>>>();

    ksum_kernel<<<BHn, 256>>>();

    dim3 gc(BHn, NSEG);              // 64 x 16
    ctx_kernel<<<gc, 256>>>();
    ctx_reduce_kernel<<<(BHn * MM * DD + 255) / 256, 256>>>();

    attn_kernel<<<dim3(BHn, NSEQ / 32), 256, ATTN_SMEM>>>();

    sgemm_nt<0><<<gg, 256>>>(pattn, Wo, bo, out, TT, EE, EE);
}

// round 3
// speedup vs baseline: 1.7173x; 1.7173x over previous
#include <cuda_runtime.h>
#include <cuda_bf16.h>
#include <math.h>
#include <stdint.h>

// Problem constants
#define BB   4
#define NSEQ 4096
#define EE   1024
#define HH   16
#define DD   64
#define MM   256
#define TT   (BB*NSEQ)     // 16384
#define BHn  (BB*HH)       // 64
#define NSEG 16

// ---------------- device scratch ----------------
__device__ float g_q[(size_t)BHn*NSEQ*DD];
__device__ float g_k[(size_t)BHn*NSEQ*DD];
__device__ float g_v[(size_t)BHn*NSEQ*DD];
__device__ float g_qf[(size_t)BHn*NSEQ*MM];
__device__ float g_kf[(size_t)BHn*NSEQ*MM];
__device__ float g_diagk[BHn*NSEQ];
__device__ float g_ksum[BHn*MM];
__device__ float g_ctxp[(size_t)NSEG*BHn*MM*DD];
__device__ float g_ctx[BHn*MM*DD];
__device__ float g_attn[(size_t)TT*EE];
__device__ float g_kstab;
__device__ __nv_bfloat16 g_ah[(size_t)TT*EE];
__device__ __nv_bfloat16 g_al[(size_t)TT*EE];
__device__ __nv_bfloat16 g_wh[(size_t)EE*EE];
__device__ __nv_bfloat16 g_wl[(size_t)EE*EE];

// ---------------- helpers ----------------
__device__ __forceinline__ void atomicMaxFloat(float* addr, float v) {
    if (v >= 0.f) atomicMax((int*)addr, __float_as_int(v));
    else          atomicMin((unsigned int*)addr, __float_as_uint(v));
}

__global__ void init_kernel() {
    if (blockIdx.x == 0 && threadIdx.x == 0) g_kstab = -INFINITY;
}

__device__ __forceinline__ uint32_t smem_u32(const void* p) {
    uint32_t a;
    asm("{ .reg .u64 t; cvta.to.shared.u64 t, %1; cvt.u32.u64 %0, t; }" : "=r"(a) : "l"(p));
    return a;
}

__device__ __forceinline__ void mma16816(float* c, const uint32_t* a, const uint32_t* b) {
    asm volatile(
        "mma.sync.aligned.m16n8k16.row.col.f32.bf16.bf16.f32 "
        "{%0,%1,%2,%3},{%4,%5,%6,%7},{%8,%9},{%0,%1,%2,%3};"
        : "+f"(c[0]), "+f"(c[1]), "+f"(c[2]), "+f"(c[3])
        : "r"(a[0]), "r"(a[1]), "r"(a[2]), "r"(a[3]), "r"(b[0]), "r"(b[1]));
}

// ---------------- fp32 -> bf16 hi/lo split ----------------
__global__ __launch_bounds__(256) void split_kernel(
    const float* __restrict__ src, __nv_bfloat16* __restrict__ hi,
    __nv_bfloat16* __restrict__ lo, int n4)
{
    const float4* s4 = (const float4*)src;
    uint2* h2 = (uint2*)hi;
    uint2* l2 = (uint2*)lo;
    for (int i = blockIdx.x * 256 + threadIdx.x; i < n4; i += gridDim.x * 256) {
        float4 v = s4[i];
        __nv_bfloat16 h0 = __float2bfloat16(v.x);
        __nv_bfloat16 h1 = __float2bfloat16(v.y);
        __nv_bfloat16 h2b = __float2bfloat16(v.z);
        __nv_bfloat16 h3 = __float2bfloat16(v.w);
        __nv_bfloat16 l0 = __float2bfloat16(v.x - __bfloat162float(h0));
        __nv_bfloat16 l1 = __float2bfloat16(v.y - __bfloat162float(h1));
        __nv_bfloat16 l2b = __float2bfloat16(v.z - __bfloat162float(h2b));
        __nv_bfloat16 l3 = __float2bfloat16(v.w - __bfloat162float(h3));
        uint2 hv, lv;
        hv.x = ((uint32_t)__bfloat16_as_ushort(h1) << 16) | __bfloat16_as_ushort(h0);
        hv.y = ((uint32_t)__bfloat16_as_ushort(h3) << 16) | __bfloat16_as_ushort(h2b);
        lv.x = ((uint32_t)__bfloat16_as_ushort(l1) << 16) | __bfloat16_as_ushort(l0);
        lv.y = ((uint32_t)__bfloat16_as_ushort(l3) << 16) | __bfloat16_as_ushort(l2b);
        h2[i] = hv;
        l2[i] = lv;
    }
}

// ---------------- bf16-split mma.sync GEMM: C = A*W^T + bias ----------------
// A [16384,1024] hi/lo bf16, W [1024,1024] row-major hi/lo bf16 (= B K-major).
// 3 passes: Ah*Wh + Ah*Wl + Al*Wh, fp32 register accumulators.
// CTA 128x128, K-chunk 32, double-buffered cp.async, 8 warps (2M x 4N), warp 64x32.
#define NCHUNK 96   // 3 * 1024/32

template<int OUT_MODE>
__global__ __launch_bounds__(256) void gemm_mma(
    const __nv_bfloat16* __restrict__ Ah, const __nv_bfloat16* __restrict__ Al,
    const __nv_bfloat16* __restrict__ Wh, const __nv_bfloat16* __restrict__ Wl,
    const float* __restrict__ bias, float* __restrict__ C)
{
    __shared__ __align__(128) char sA[2][8192];   // 128 rows x 64B, xor-swizzled
    __shared__ __align__(128) char sB[2][8192];

    const int tid  = threadIdx.x;
    const int lane = tid & 31;
    const int wid  = tid >> 5;
    const int wm   = wid & 1;     // 2 warps along M
    const int wn   = wid >> 1;    // 4 warps along N
    const int bm   = blockIdx.y * 128;
    const int bn   = blockIdx.x * 128;

    const __nv_bfloat16* pA[3] = {Ah, Ah, Al};
    const __nv_bfloat16* pB[3] = {Wh, Wl, Wh};

    float c[4][4][4];
#pragma unroll
    for (int i = 0; i < 4; i++)
#pragma unroll
        for (int j = 0; j < 4; j++)
#pragma unroll
            for (int q = 0; q < 4; q++) c[i][j][q] = 0.f;

    const uint32_t aS0 = smem_u32(sA[0]);
    const uint32_t bS0 = smem_u32(sB[0]);

    // prefetch one 128x32 chunk pair into buffer `buf`
    auto prefetch = [&](int s, int buf) {
        const int ph = s >> 5;
        const int kk = (s & 31) << 5;
        const __nv_bfloat16* gA = pA[ph];
        const __nv_bfloat16* gB = pB[ph];
        const uint32_t aB = aS0 + buf * 8192;
        const uint32_t bB = bS0 + buf * 8192;
#pragma unroll
        for (int it = 0; it < 2; it++) {
            int idx = it * 256 + tid;        // 0..511
            int row = idx >> 2;              // 0..127
            int pb  = idx & 3;               // 16B block within row
            uint32_t doff = row * 64 + ((pb ^ ((row >> 1) & 3)) << 4);
            const void* srcA = gA + (size_t)(bm + row) * EE + kk + pb * 8;
            const void* srcB = gB + (size_t)(bn + row) * EE + kk + pb * 8;
            asm volatile("cp.async.cg.shared.global [%0], [%1], 16;" :: "r"(aB + doff), "l"(srcA));
            asm volatile("cp.async.cg.shared.global [%0], [%1], 16;" :: "r"(bB + doff), "l"(srcB));
        }
        asm volatile("cp.async.commit_group;" ::: "memory");
    };

    prefetch(0, 0);

    for (int s = 0; s < NCHUNK; s++) {
        const int buf = s & 1;
        if (s + 1 < NCHUNK) {
            prefetch(s + 1, buf ^ 1);
            asm volatile("cp.async.wait_group 1;" ::: "memory");
        } else {
            asm volatile("cp.async.wait_group 0;" ::: "memory");
        }
        __syncthreads();

        const char* cA = sA[buf];
        const char* cB = sB[buf];
#pragma unroll
        for (int ks = 0; ks < 2; ks++) {
            const int p = ks * 8 + (lane & 3);     // pos4 (2-elem unit)
            // B fragments: 4 n-tiles of 8
            uint32_t bf[4][2];
#pragma unroll
            for (int j = 0; j < 4; j++) {
                int n0 = wn * 32 + j * 8 + (lane >> 2);
                int g  = ((n0 >> 1) & 3) << 2;
                bf[j][0] = *(const uint32_t*)(cB + n0 * 64 + (((p    ) ^ g) << 2));
                bf[j][1] = *(const uint32_t*)(cB + n0 * 64 + (((p + 4) ^ g) << 2));
            }
#pragma unroll
            for (int i = 0; i < 4; i++) {
                int r0 = wm * 64 + i * 16 + (lane >> 2);
                int r1 = r0 + 8;
                int g0 = ((r0 >> 1) & 3) << 2;
                int g1 = ((r1 >> 1) & 3) << 2;
                uint32_t af[4];
                af[0] = *(const uint32_t*)(cA + r0 * 64 + (((p    ) ^ g0) << 2));
                af[1] = *(const uint32_t*)(cA + r1 * 64 + (((p    ) ^ g1) << 2));
                af[2] = *(const uint32_t*)(cA + r0 * 64 + (((p + 4) ^ g0) << 2));
                af[3] = *(const uint32_t*)(cA + r1 * 64 + (((p + 4) ^ g1) << 2));
#pragma unroll
                for (int j = 0; j < 4; j++)
                    mma16816(c[i][j], af, bf[j]);
            }
        }
        __syncthreads();
    }

    // epilogue: bias + store
#pragma unroll
    for (int i = 0; i < 4; i++) {
        int r = bm + wm * 64 + i * 16 + (lane >> 2);
#pragma unroll
        for (int j = 0; j < 4; j++) {
            int col = bn + wn * 32 + j * 8 + (lane & 3) * 2;
            float b0 = bias[col], b1 = bias[col + 1];
            float2 v0 = make_float2(c[i][j][0] + b0, c[i][j][1] + b1);
            float2 v1 = make_float2(c[i][j][2] + b0, c[i][j][3] + b1);
            if (OUT_MODE == 0) {
                *(float2*)(C + (size_t)r * EE + col)       = v0;
                *(float2*)(C + (size_t)(r + 8) * EE + col) = v1;
            } else {
                int h_ = col >> 6, d0 = col & 63;
                int b_ = r >> 12, n_ = r & 4095;
                size_t base = ((size_t)(b_ * HH + h_) * NSEQ);
                *(float2*)(C + (base + n_)     * DD + d0) = v0;
                *(float2*)(C + (base + n_ + 8) * DD + d0) = v1;
            }
        }
    }
}

// ---------------- FAVOR+ feature kernel ----------------
__global__ __launch_bounds__(256) void feat_kernel(
    const float* __restrict__ X,    // [BH, N, D]
    const float* __restrict__ proj, // [M, D]
    float* __restrict__ F,          // [BH, N, M]
    float* __restrict__ diag_out,
    int is_query)
{
    extern __shared__ float sm[];
    float* sPT = sm;                // [D][M]
    float* sX  = sm + DD * MM;      // [32][D]
    __shared__ float s_wmax[8];

    const int tid = threadIdx.x;
    const int bh  = blockIdx.x;
    const int n0  = blockIdx.y * 32;

    {
        const float4* pr = (const float4*)(proj + tid * DD);
#pragma unroll
        for (int t = 0; t < 16; t++) {
            float4 v = pr[t];
            int d = t * 4;
            sPT[(d + 0) * MM + tid] = v.x;
            sPT[(d + 1) * MM + tid] = v.y;
            sPT[(d + 2) * MM + tid] = v.z;
            sPT[(d + 3) * MM + tid] = v.w;
        }
    }
    {
        const float SC = 0.3535533905932738f;  // 64^-0.25
        const float4* xr = (const float4*)(X + ((size_t)bh * NSEQ + n0) * DD);
        float4* sx4 = (float4*)sX;
#pragma unroll
        for (int i = 0; i < 2; i++) {
            int f = tid * 2 + i;
            float4 v = xr[f];
            sx4[f] = make_float4(v.x * SC, v.y * SC, v.z * SC, v.w * SC);
        }
    }
    __syncthreads();

    const int lane = tid & 31;
    const int w    = tid >> 5;
    const int m0   = lane * 8;

    float acc[4][8];
#pragma unroll
    for (int r = 0; r < 4; r++)
#pragma unroll
        for (int j = 0; j < 8; j++) acc[r][j] = 0.f;

#pragma unroll 16
    for (int d = 0; d < DD; d++) {
        float b[8];
        *(float4*)(b)     = *(const float4*)(&sPT[d * MM + m0]);
        *(float4*)(b + 4) = *(const float4*)(&sPT[d * MM + m0 + 4]);
#pragma unroll
        for (int r = 0; r < 4; r++) {
            float a = sX[(w * 4 + r) * DD + d];
#pragma unroll
            for (int j = 0; j < 8; j++) acc[r][j] += a * b[j];
        }
    }

    float dg[4];
#pragma unroll
    for (int r = 0; r < 4; r++) {
        const float* xr = &sX[(w * 4 + r) * DD];
        float x0 = xr[lane * 2], x1 = xr[lane * 2 + 1];
        float p = x0 * x0 + x1 * x1;
#pragma unroll
        for (int o = 16; o > 0; o >>= 1) p += __shfl_xor_sync(0xffffffffu, p, o);
        dg[r] = 0.5f * p;
    }

    const float RATIO = 0.0625f;
    const float EPSK  = 1e-4f;

    if (is_query) {
#pragma unroll
        for (int r = 0; r < 4; r++) {
            float mx = acc[r][0];
#pragma unroll
            for (int j = 1; j < 8; j++) mx = fmaxf(mx, acc[r][j]);
#pragma unroll
            for (int o = 16; o > 0; o >>= 1)
                mx = fmaxf(mx, __shfl_xor_sync(0xffffffffu, mx, o));
            float sub = dg[r] + mx;
            float o8[8];
#pragma unroll
            for (int j = 0; j < 8; j++)
                o8[j] = RATIO * (expf(acc[r][j] - sub) + EPSK);
            float4* dst = (float4*)(F + ((size_t)bh * NSEQ + n0 + w * 4 + r) * MM + m0);
            dst[0] = *(float4*)(o8);
            dst[1] = *(float4*)(o8 + 4);
        }
    } else {
        float wmx = -INFINITY;
#pragma unroll
        for (int r = 0; r < 4; r++) {
            float4* dst = (float4*)(F + ((size_t)bh * NSEQ + n0 + w * 4 + r) * MM + m0);
            dst[0] = *(float4*)(&acc[r][0]);
            dst[1] = *(float4*)(&acc[r][4]);
#pragma unroll
            for (int j = 0; j < 8; j++) wmx = fmaxf(wmx, acc[r][j]);
        }
        if (lane == 0) {
#pragma unroll
            for (int r = 0; r < 4; r++)
                diag_out[bh * NSEQ + n0 + w * 4 + r] = dg[r];
        }
#pragma unroll
        for (int o = 16; o > 0; o >>= 1)
            wmx = fmaxf(wmx, __shfl_xor_sync(0xffffffffu, wmx, o));
        if (lane == 0) s_wmax[w] = wmx;
        __syncthreads();
        if (tid == 0) {
            float m = s_wmax[0];
#pragma unroll
            for (int i = 1; i < 8; i++) m = fmaxf(m, s_wmax[i]);
            atomicMaxFloat(&g_kstab, m);
        }
    }
}

// ---------------- key features pass 2 ----------------
__global__ __launch_bounds__(256) void kpass2_kernel() {
    const float RATIO = 0.0625f;
    const float EPSK  = 1e-4f;
    const float stab  = g_kstab;
    const size_t total4 = (size_t)BHn * NSEQ * MM / 4;
    float4* kf4 = (float4*)g_kf;
    for (size_t i = (size_t)blockIdx.x * blockDim.x + threadIdx.x; i < total4;
         i += (size_t)gridDim.x * blockDim.x) {
        size_t row = (i * 4) / MM;
        float sub = g_diagk[row] + stab;
        float4 v = kf4[i];
        v.x = RATIO * (expf(v.x - sub) + EPSK);
        v.y = RATIO * (expf(v.y - sub) + EPSK);
        v.z = RATIO * (expf(v.z - sub) + EPSK);
        v.w = RATIO * (expf(v.w - sub) + EPSK);
        kf4[i] = v;
    }
}

// ---------------- k_sum ----------------
__global__ __launch_bounds__(256) void ksum_kernel() {
    int bh = blockIdx.x;
    int m  = threadIdx.x;
    const float* base = g_kf + (size_t)bh * NSEQ * MM + m;
    float s = 0.f;
#pragma unroll 8
    for (int n = 0; n < NSEQ; n++) s += base[(size_t)n * MM];
    g_ksum[bh * MM + m] = s;
}

// ---------------- context partials ----------------
__global__ __launch_bounds__(256) void ctx_kernel() {
    __shared__ float  sK[16][MM];
    __shared__ float4 sV[16][16];
    const int bh  = blockIdx.x;
    const int seg = blockIdx.y;
    const int tid = threadIdx.x;
    const int tx  = tid & 15;
    const int ty  = tid >> 4;

    float4 acc[16];
#pragma unroll
    for (int i = 0; i < 16; i++) acc[i] = make_float4(0.f, 0.f, 0.f, 0.f);

    const int nbase = seg * (NSEQ / NSEG);
    for (int n0 = nbase; n0 < nbase + NSEQ / NSEG; n0 += 16) {
        const float* kb = g_kf + ((size_t)bh * NSEQ + n0) * MM;
#pragma unroll
        for (int t = 0; t < 16; t++) {
            int idx = tid + t * 256;
            sK[idx >> 8][idx & 255] = kb[idx];
        }
        const float* vb = g_v + ((size_t)bh * NSEQ + n0) * DD;
        float* sVf = (float*)sV;
#pragma unroll
        for (int t = 0; t < 4; t++) {
            int idx = tid + t * 256;
            sVf[idx] = vb[idx];
        }
        __syncthreads();
#pragma unroll
        for (int r = 0; r < 16; r++) {
            float4 bv = sV[r][tx];
#pragma unroll
            for (int i = 0; i < 16; i++) {
                float a = sK[r][ty * 16 + i];
                acc[i].x += a * bv.x; acc[i].y += a * bv.y;
                acc[i].z += a * bv.z; acc[i].w += a * bv.w;
            }
        }
        __syncthreads();
    }
    float4* cp = (float4*)(g_ctxp + ((size_t)seg * BHn + bh) * MM * DD);
#pragma unroll
    for (int i = 0; i < 16; i++) {
        int m = ty * 16 + i;
        cp[(m * DD) / 4 + tx] = acc[i];
    }
}

__global__ __launch_bounds__(256) void ctx_reduce_kernel() {
    int i = blockIdx.x * 256 + threadIdx.x;
    if (i < BHn * MM * DD) {
        float s = 0.f;
#pragma unroll
        for (int seg = 0; seg < NSEG; seg++)
            s += g_ctxp[(size_t)seg * BHn * MM * DD + i];
        g_ctx[i] = s;
    }
}

// ---------------- attention combine ----------------
__global__ __launch_bounds__(256) void attn_kernel() {
    extern __shared__ float sm[];
    float* sCtx = sm;                  // [M][D]
    float* sQF  = sm + MM * DD;        // [32][M]
    float* sKs  = sQF + 32 * MM;       // [M]
    const int bh = blockIdx.x;
    const int b  = bh >> 4;
    const int h  = bh & 15;
    const int n0 = blockIdx.y * 32;
    const int tid  = threadIdx.x;
    const int lane = tid & 31;
    const int w    = tid >> 5;

    const float* cb = g_ctx + (size_t)bh * MM * DD;
#pragma unroll
    for (int t = 0; t < 64; t++) sCtx[tid + t * 256] = cb[tid + t * 256];
    const float* qb = g_qf + ((size_t)bh * NSEQ + n0) * MM;
#pragma unroll
    for (int t = 0; t < 32; t++) sQF[tid + t * 256] = qb[tid + t * 256];
    sKs[tid] = g_ksum[bh * MM + tid];
    __syncthreads();

    const float2* sCtx2 = (const float2*)sCtx;
#pragma unroll
    for (int r4 = 0; r4 < 4; r4++) {
        int r = w * 4 + r4;
        const float* q = &sQF[r * MM];
        float ax = 0.f, ay = 0.f, dp = 0.f;
#pragma unroll 8
        for (int m = 0; m < MM; m++) {
            float qv = q[m];
            dp += qv * sKs[m];
            float2 cc = sCtx2[m * 32 + lane];
            ax += qv * cc.x; ay += qv * cc.y;
        }
        float dinv = 1.f / dp;
        float2* outp = (float2*)(g_attn + ((size_t)(b * NSEQ + n0 + r)) * EE + h * DD);
        outp[lane] = make_float2(ax * dinv, ay * dinv);
    }
}

// ---------------- launch ----------------
extern "C" void kernel_launch(void* const* d_in, const int* in_sizes, int n_in,
                              void* d_out, int out_size) {
    const float* x    = (const float*)d_in[0];
    const float* Wq   = (const float*)d_in[1];
    const float* bq   = (const float*)d_in[2];
    const float* Wk   = (const float*)d_in[3];
    const float* bk   = (const float*)d_in[4];
    const float* Wv   = (const float*)d_in[5];
    const float* bv   = (const float*)d_in[6];
    const float* Wo   = (const float*)d_in[7];
    const float* bo   = (const float*)d_in[8];
    const float* proj = (const float*)d_in[9];
    float* out = (float*)d_out;

    float *pq, *pk, *pv, *pqf, *pkf, *pdg, *pattn;
    __nv_bfloat16 *pah, *pal, *pwh, *pwl;
    cudaGetSymbolAddress((void**)&pq,    g_q);
    cudaGetSymbolAddress((void**)&pk,    g_k);
    cudaGetSymbolAddress((void**)&pv,    g_v);
    cudaGetSymbolAddress((void**)&pqf,   g_qf);
    cudaGetSymbolAddress((void**)&pkf,   g_kf);
    cudaGetSymbolAddress((void**)&pdg,   g_diagk);
    cudaGetSymbolAddress((void**)&pattn, g_attn);
    cudaGetSymbolAddress((void**)&pah,   g_ah);
    cudaGetSymbolAddress((void**)&pal,   g_al);
    cudaGetSymbolAddress((void**)&pwh,   g_wh);
    cudaGetSymbolAddress((void**)&pwl,   g_wl);

    const int FEAT_SMEM = (DD * MM + 32 * DD) * (int)sizeof(float);
    const int ATTN_SMEM = (MM * DD + 32 * MM + MM) * (int)sizeof(float);
    cudaFuncSetAttribute(feat_kernel, cudaFuncAttributeMaxDynamicSharedMemorySize, FEAT_SMEM);
    cudaFuncSetAttribute(attn_kernel, cudaFuncAttributeMaxDynamicSharedMemorySize, ATTN_SMEM);

    init_kernel<<<1, 32>>>();

    // split x into bf16 hi/lo (shared by Q/K/V gemms)
    split_kernel<<<2048, 256>>>(x, pah, pal, TT * EE / 4);

    dim3 gg(EE / 128, TT / 128);     // 8 x 128 CTAs

    split_kernel<<<512, 256>>>(Wq, pwh, pwl, EE * EE / 4);
    gemm_mma<1><<<gg, 256>>>(pah, pal, pwh, pwl, bq, pq);
    split_kernel<<<512, 256>>>(Wk, pwh, pwl, EE * EE / 4);
    gemm_mma<1><<<gg, 256>>>(pah, pal, pwh, pwl, bk, pk);
    split_kernel<<<512, 256>>>(Wv, pwh, pwl, EE * EE / 4);
    gemm_mma<1><<<gg, 256>>>(pah, pal, pwh, pwl, bv, pv);

    dim3 gf(BHn, NSEQ / 32);
    feat_kernel<<<gf, 256, FEAT_SMEM>>>(pq, proj, pqf, nullptr, 1);
    feat_kernel<<<gf, 256, FEAT_SMEM>>>(pk, proj, pkf, pdg, 0);

    kpass2_kernel<<<8192, 256>>>();
    ksum_kernel<<<BHn, 256>>>();

    dim3 gc(BHn, NSEG);
    ctx_kernel<<<gc, 256>>>();
    ctx_reduce_kernel<<<(BHn * MM * DD + 255) / 256, 256>>>();

    attn_kernel<<<dim3(BHn, NSEQ / 32), 256, ATTN_SMEM>>>();

    // output projection
    split_kernel<<<2048, 256>>>(pattn, pah, pal, TT * EE / 4);
    split_kernel<<<512, 256>>>(Wo, pwh, pwl, EE * EE / 4);
    gemm_mma<0><<<gg, 256>>>(pah, pal, pwh, pwl, bo, out);
}

// round 4
// speedup vs baseline: 2.0783x; 1.2102x over previous
#include <cuda_runtime.h>
#include <cuda_bf16.h>
#include <math.h>
#include <stdint.h>

// Problem constants
#define BB   4
#define NSEQ 4096
#define EE   1024
#define HH   16
#define DD   64
#define MM   256
#define TT   (BB*NSEQ)     // 16384
#define BHn  (BB*HH)       // 64
#define NSEG 16

#define RATIO 0.0625f
#define EPSK  1e-4f
#define SCQ   0.3535533905932738f   // 64^-0.25

// ---------------- device scratch ----------------
__device__ float g_q[(size_t)BHn*NSEQ*DD];
__device__ float g_k[(size_t)BHn*NSEQ*DD];
__device__ float g_v[(size_t)BHn*NSEQ*DD];
__device__ float g_ksum[BHn*MM];
__device__ float g_ksump[(size_t)NSEG*BHn*MM];
__device__ float g_ctxp[(size_t)NSEG*BHn*MM*DD];
__device__ float g_ctx[BHn*MM*DD];
__device__ float g_attn[(size_t)TT*EE];
__device__ float g_kstab;
__device__ __nv_bfloat16 g_ah[(size_t)TT*EE];
__device__ __nv_bfloat16 g_al[(size_t)TT*EE];
__device__ __nv_bfloat16 g_wh[(size_t)EE*EE];
__device__ __nv_bfloat16 g_wl[(size_t)EE*EE];

// ---------------- helpers ----------------
__device__ __forceinline__ void atomicMaxFloat(float* addr, float v) {
    if (v >= 0.f) atomicMax((int*)addr, __float_as_int(v));
    else          atomicMin((unsigned int*)addr, __float_as_uint(v));
}

__global__ void init_kernel() {
    if (blockIdx.x == 0 && threadIdx.x == 0) g_kstab = -INFINITY;
}

__device__ __forceinline__ uint32_t smem_u32(const void* p) {
    uint32_t a;
    asm("{ .reg .u64 t; cvta.to.shared.u64 t, %1; cvt.u32.u64 %0, t; }" : "=r"(a) : "l"(p));
    return a;
}

__device__ __forceinline__ void mma16816(float* c, const uint32_t* a, const uint32_t* b) {
    asm volatile(
        "mma.sync.aligned.m16n8k16.row.col.f32.bf16.bf16.f32 "
        "{%0,%1,%2,%3},{%4,%5,%6,%7},{%8,%9},{%0,%1,%2,%3};"
        : "+f"(c[0]), "+f"(c[1]), "+f"(c[2]), "+f"(c[3])
        : "r"(a[0]), "r"(a[1]), "r"(a[2]), "r"(a[3]), "r"(b[0]), "r"(b[1]));
}

// packed fp32x2 (sm_100+ base PTX)
__device__ __forceinline__ void fma2(unsigned long long& d, unsigned long long a, unsigned long long b) {
    asm("fma.rn.f32x2 %0, %1, %2, %0;" : "+l"(d) : "l"(a), "l"(b));
}
__device__ __forceinline__ unsigned long long pack2(float x) {
    unsigned long long r;
    asm("mov.b64 %0, {%1, %1};" : "=l"(r) : "f"(x));
    return r;
}
__device__ __forceinline__ float2 unpack2(unsigned long long v) {
    float2 f;
    asm("mov.b64 {%0, %1}, %2;" : "=f"(f.x), "=f"(f.y) : "l"(v));
    return f;
}

// ---------------- fp32 -> bf16 hi/lo split ----------------
__global__ __launch_bounds__(256) void split_kernel(
    const float* __restrict__ src, __nv_bfloat16* __restrict__ hi,
    __nv_bfloat16* __restrict__ lo, int n4)
{
    const float4* s4 = (const float4*)src;
    uint2* h2 = (uint2*)hi;
    uint2* l2 = (uint2*)lo;
    for (int i = blockIdx.x * 256 + threadIdx.x; i < n4; i += gridDim.x * 256) {
        float4 v = s4[i];
        __nv_bfloat16 h0 = __float2bfloat16(v.x);
        __nv_bfloat16 h1 = __float2bfloat16(v.y);
        __nv_bfloat16 h2b = __float2bfloat16(v.z);
        __nv_bfloat16 h3 = __float2bfloat16(v.w);
        __nv_bfloat16 l0 = __float2bfloat16(v.x - __bfloat162float(h0));
        __nv_bfloat16 l1 = __float2bfloat16(v.y - __bfloat162float(h1));
        __nv_bfloat16 l2b = __float2bfloat16(v.z - __bfloat162float(h2b));
        __nv_bfloat16 l3 = __float2bfloat16(v.w - __bfloat162float(h3));
        uint2 hv, lv;
        hv.x = ((uint32_t)__bfloat16_as_ushort(h1) << 16) | __bfloat16_as_ushort(h0);
        hv.y = ((uint32_t)__bfloat16_as_ushort(h3) << 16) | __bfloat16_as_ushort(h2b);
        lv.x = ((uint32_t)__bfloat16_as_ushort(l1) << 16) | __bfloat16_as_ushort(l0);
        lv.y = ((uint32_t)__bfloat16_as_ushort(l3) << 16) | __bfloat16_as_ushort(l2b);
        h2[i] = hv;
        l2[i] = lv;
    }
}

// ---------------- bf16-split mma.sync GEMM (unchanged from R3) ----------------
#define NCHUNK 96   // 3 * 1024/32

template<int OUT_MODE>
__global__ __launch_bounds__(256) void gemm_mma(
    const __nv_bfloat16* __restrict__ Ah, const __nv_bfloat16* __restrict__ Al,
    const __nv_bfloat16* __restrict__ Wh, const __nv_bfloat16* __restrict__ Wl,
    const float* __restrict__ bias, float* __restrict__ C)
{
    __shared__ __align__(128) char sA[2][8192];
    __shared__ __align__(128) char sB[2][8192];

    const int tid  = threadIdx.x;
    const int lane = tid & 31;
    const int wid  = tid >> 5;
    const int wm   = wid & 1;
    const int wn   = wid >> 1;
    const int bm   = blockIdx.y * 128;
    const int bn   = blockIdx.x * 128;

    const __nv_bfloat16* pA[3] = {Ah, Ah, Al};
    const __nv_bfloat16* pB[3] = {Wh, Wl, Wh};

    float c[4][4][4];
#pragma unroll
    for (int i = 0; i < 4; i++)
#pragma unroll
        for (int j = 0; j < 4; j++)
#pragma unroll
            for (int q = 0; q < 4; q++) c[i][j][q] = 0.f;

    const uint32_t aS0 = smem_u32(sA[0]);
    const uint32_t bS0 = smem_u32(sB[0]);

    auto prefetch = [&](int s, int buf) {
        const int ph = s >> 5;
        const int kk = (s & 31) << 5;
        const __nv_bfloat16* gA = pA[ph];
        const __nv_bfloat16* gB = pB[ph];
        const uint32_t aB = aS0 + buf * 8192;
        const uint32_t bB = bS0 + buf * 8192;
#pragma unroll
        for (int it = 0; it < 2; it++) {
            int idx = it * 256 + tid;
            int row = idx >> 2;
            int pb  = idx & 3;
            uint32_t doff = row * 64 + ((pb ^ ((row >> 1) & 3)) << 4);
            const void* srcA = gA + (size_t)(bm + row) * EE + kk + pb * 8;
            const void* srcB = gB + (size_t)(bn + row) * EE + kk + pb * 8;
            asm volatile("cp.async.cg.shared.global [%0], [%1], 16;" :: "r"(aB + doff), "l"(srcA));
            asm volatile("cp.async.cg.shared.global [%0], [%1], 16;" :: "r"(bB + doff), "l"(srcB));
        }
        asm volatile("cp.async.commit_group;" ::: "memory");
    };

    prefetch(0, 0);

    for (int s = 0; s < NCHUNK; s++) {
        const int buf = s & 1;
        if (s + 1 < NCHUNK) {
            prefetch(s + 1, buf ^ 1);
            asm volatile("cp.async.wait_group 1;" ::: "memory");
        } else {
            asm volatile("cp.async.wait_group 0;" ::: "memory");
        }
        __syncthreads();

        const char* cA = sA[buf];
        const char* cB = sB[buf];
#pragma unroll
        for (int ks = 0; ks < 2; ks++) {
            const int p = ks * 8 + (lane & 3);
            uint32_t bf[4][2];
#pragma unroll
            for (int j = 0; j < 4; j++) {
                int n0 = wn * 32 + j * 8 + (lane >> 2);
                int g  = ((n0 >> 1) & 3) << 2;
                bf[j][0] = *(const uint32_t*)(cB + n0 * 64 + (((p    ) ^ g) << 2));
                bf[j][1] = *(const uint32_t*)(cB + n0 * 64 + (((p + 4) ^ g) << 2));
            }
#pragma unroll
            for (int i = 0; i < 4; i++) {
                int r0 = wm * 64 + i * 16 + (lane >> 2);
                int r1 = r0 + 8;
                int g0 = ((r0 >> 1) & 3) << 2;
                int g1 = ((r1 >> 1) & 3) << 2;
                uint32_t af[4];
                af[0] = *(const uint32_t*)(cA + r0 * 64 + (((p    ) ^ g0) << 2));
                af[1] = *(const uint32_t*)(cA + r1 * 64 + (((p    ) ^ g1) << 2));
                af[2] = *(const uint32_t*)(cA + r0 * 64 + (((p + 4) ^ g0) << 2));
                af[3] = *(const uint32_t*)(cA + r1 * 64 + (((p + 4) ^ g1) << 2));
#pragma unroll
                for (int j = 0; j < 4; j++)
                    mma16816(c[i][j], af, bf[j]);
            }
        }
        __syncthreads();
    }

#pragma unroll
    for (int i = 0; i < 4; i++) {
        int r = bm + wm * 64 + i * 16 + (lane >> 2);
#pragma unroll
        for (int j = 0; j < 4; j++) {
            int col = bn + wn * 32 + j * 8 + (lane & 3) * 2;
            float b0 = bias[col], b1 = bias[col + 1];
            float2 v0 = make_float2(c[i][j][0] + b0, c[i][j][1] + b1);
            float2 v1 = make_float2(c[i][j][2] + b0, c[i][j][3] + b1);
            if (OUT_MODE == 0) {
                *(float2*)(C + (size_t)r * EE + col)       = v0;
                *(float2*)(C + (size_t)(r + 8) * EE + col) = v1;
            } else {
                int h_ = col >> 6, d0 = col & 63;
                int b_ = r >> 12, n_ = r & 4095;
                size_t base = ((size_t)(b_ * HH + h_) * NSEQ);
                *(float2*)(C + (base + n_)     * DD + d0) = v0;
                *(float2*)(C + (base + n_ + 8) * DD + d0) = v1;
            }
        }
    }
}

// ---------------- pass 1: global max of dd_k ----------------
// grid (BHn, 16), block 256: each block does 256 rows (8 tiles of 32).
__global__ __launch_bounds__(256) void kmax_kernel(
    const float* __restrict__ X, const float* __restrict__ proj)
{
    extern __shared__ float sm[];
    float* sPT = sm;             // [64][256]
    float* sX  = sm + DD * MM;   // [32][64]
    __shared__ float swm[8];

    const int tid = threadIdx.x;
    const int bh  = blockIdx.x;
    const int nbase = blockIdx.y * 256;
    const int lane = tid & 31;
    const int w    = tid >> 5;
    const int m0   = lane * 8;

    {
        const float4* pr = (const float4*)(proj + tid * DD);
#pragma unroll
        for (int t = 0; t < 16; t++) {
            float4 v = pr[t];
            int d = t * 4;
            sPT[(d + 0) * MM + tid] = v.x;
            sPT[(d + 1) * MM + tid] = v.y;
            sPT[(d + 2) * MM + tid] = v.z;
            sPT[(d + 3) * MM + tid] = v.w;
        }
    }

    float vmax = -1e30f;
    for (int t = 0; t < 8; t++) {
        const int n0 = nbase + t * 32;
        __syncthreads();
        {
            const float4* xr = (const float4*)(X + ((size_t)bh * NSEQ + n0) * DD);
            float4* sx4 = (float4*)sX;
#pragma unroll
            for (int i = 0; i < 2; i++) {
                int f = tid * 2 + i;
                float4 v = xr[f];
                sx4[f] = make_float4(v.x * SCQ, v.y * SCQ, v.z * SCQ, v.w * SCQ);
            }
        }
        __syncthreads();

        unsigned long long a2[4][4];
#pragma unroll
        for (int r = 0; r < 4; r++)
#pragma unroll
            for (int j = 0; j < 4; j++) a2[r][j] = 0ull;

#pragma unroll 8
        for (int d = 0; d < DD; d++) {
            const ulonglong2* bp = (const ulonglong2*)&sPT[d * MM + m0];
            ulonglong2 b01 = bp[0], b23 = bp[1];
#pragma unroll
            for (int r = 0; r < 4; r++) {
                unsigned long long av = pack2(sX[(w * 4 + r) * DD + d]);
                fma2(a2[r][0], av, b01.x); fma2(a2[r][1], av, b01.y);
                fma2(a2[r][2], av, b23.x); fma2(a2[r][3], av, b23.y);
            }
        }
#pragma unroll
        for (int r = 0; r < 4; r++)
#pragma unroll
            for (int j = 0; j < 4; j++) {
                float2 f = unpack2(a2[r][j]);
                vmax = fmaxf(vmax, fmaxf(f.x, f.y));
            }
    }
#pragma unroll
    for (int o = 16; o > 0; o >>= 1)
        vmax = fmaxf(vmax, __shfl_xor_sync(0xffffffffu, vmax, o));
    if (lane == 0) swm[w] = vmax;
    __syncthreads();
    if (tid == 0) {
        float m = swm[0];
#pragma unroll
        for (int i = 1; i < 8; i++) m = fmaxf(m, swm[i]);
        atomicMaxFloat(&g_kstab, m);
    }
}

// ---------------- pass 2: fused kf recompute + context + ksum partials ----------------
// grid (BHn, NSEG), block 256. Each block: 256 n-rows (8 tiles of 32).
__global__ __launch_bounds__(256, 2) void ctx_fused(
    const float* __restrict__ K, const float* __restrict__ V,
    const float* __restrict__ proj)
{
    extern __shared__ float sm[];
    float* sPT = sm;               // [64][256]   64 KB
    float* sKF = sPT + DD * MM;    // [32][256]   32 KB
    float* sXk = sKF + 32 * MM;    // [32][64]     8 KB
    float* sV  = sXk + 32 * DD;    // [32][64]     8 KB

    const int tid = threadIdx.x;
    const int bh  = blockIdx.x;
    const int seg = blockIdx.y;
    const int lane = tid & 31;
    const int w    = tid >> 5;
    const int m0   = lane * 8;
    const int tx   = tid & 15;     // d group (4 d)
    const int ty   = tid >> 4;     // m group (16 m)

    {
        const float4* pr = (const float4*)(proj + tid * DD);
#pragma unroll
        for (int t = 0; t < 16; t++) {
            float4 v = pr[t];
            int d = t * 4;
            sPT[(d + 0) * MM + tid] = v.x;
            sPT[(d + 1) * MM + tid] = v.y;
            sPT[(d + 2) * MM + tid] = v.z;
            sPT[(d + 3) * MM + tid] = v.w;
        }
    }
    const float stab = g_kstab;

    unsigned long long cacc[16][2];   // ctx acc: 16 m x 4 d (as 2x f32x2)
#pragma unroll
    for (int i = 0; i < 16; i++) { cacc[i][0] = 0ull; cacc[i][1] = 0ull; }
    float kacc = 0.f;

    for (int it = 0; it < 8; it++) {
        const int n0 = seg * 256 + it * 32;
        __syncthreads();
        {
            const float4* kr = (const float4*)(K + ((size_t)bh * NSEQ + n0) * DD);
            const float4* vr = (const float4*)(V + ((size_t)bh * NSEQ + n0) * DD);
            float4* sk4 = (float4*)sXk;
            float4* sv4 = (float4*)sV;
#pragma unroll
            for (int i = 0; i < 2; i++) {
                int f = tid * 2 + i;
                float4 kv = kr[f];
                sk4[f] = make_float4(kv.x * SCQ, kv.y * SCQ, kv.z * SCQ, kv.w * SCQ);
                sv4[f] = vr[f];
            }
        }
        __syncthreads();

        // dd + exp -> sKF (4 rows per warp)
        {
            unsigned long long a2[4][4];
#pragma unroll
            for (int r = 0; r < 4; r++)
#pragma unroll
                for (int j = 0; j < 4; j++) a2[r][j] = 0ull;

#pragma unroll 8
            for (int d = 0; d < DD; d++) {
                const ulonglong2* bp = (const ulonglong2*)&sPT[d * MM + m0];
                ulonglong2 b01 = bp[0], b23 = bp[1];
#pragma unroll
                for (int r = 0; r < 4; r++) {
                    unsigned long long av = pack2(sXk[(w * 4 + r) * DD + d]);
                    fma2(a2[r][0], av, b01.x); fma2(a2[r][1], av, b01.y);
                    fma2(a2[r][2], av, b23.x); fma2(a2[r][3], av, b23.y);
                }
            }
#pragma unroll
            for (int r = 0; r < 4; r++) {
                const float* xr = &sXk[(w * 4 + r) * DD];
                float x0 = xr[lane * 2], x1 = xr[lane * 2 + 1];
                float p = x0 * x0 + x1 * x1;
#pragma unroll
                for (int o = 16; o > 0; o >>= 1) p += __shfl_xor_sync(0xffffffffu, p, o);
                float sub = 0.5f * p + stab;
                float o8[8];
#pragma unroll
                for (int j = 0; j < 4; j++) {
                    float2 f = unpack2(a2[r][j]);
                    o8[j * 2]     = RATIO * (__expf(f.x - sub) + EPSK);
                    o8[j * 2 + 1] = RATIO * (__expf(f.y - sub) + EPSK);
                }
                float4* dst = (float4*)&sKF[(w * 4 + r) * MM + m0];
                dst[0] = *(float4*)(o8);
                dst[1] = *(float4*)(o8 + 4);
            }
        }
        __syncthreads();

        // ksum partial
#pragma unroll
        for (int r = 0; r < 32; r++) kacc += sKF[r * MM + tid];

        // ctx partial: thread (ty, tx): 16 m x 4 d
        const ulonglong2* sV2 = (const ulonglong2*)sV;
#pragma unroll 4
        for (int r = 0; r < 32; r++) {
            ulonglong2 bv = sV2[r * 16 + tx];
            const float* kf = &sKF[r * MM + ty * 16];
#pragma unroll
            for (int i = 0; i < 16; i++) {
                unsigned long long av = pack2(kf[i]);
                fma2(cacc[i][0], av, bv.x);
                fma2(cacc[i][1], av, bv.y);
            }
        }
    }

    g_ksump[((size_t)seg * BHn + bh) * MM + tid] = kacc;
    float* cp = g_ctxp + ((size_t)seg * BHn + bh) * MM * DD;
#pragma unroll
    for (int i = 0; i < 16; i++) {
        float2 f0 = unpack2(cacc[i][0]);
        float2 f1 = unpack2(cacc[i][1]);
        *(float4*)(cp + (ty * 16 + i) * DD + tx * 4) = make_float4(f0.x, f0.y, f1.x, f1.y);
    }
}

// ---------------- reduce ctx + ksum partials ----------------
__global__ __launch_bounds__(256) void ctx_reduce_kernel() {
    int i = blockIdx.x * 256 + threadIdx.x;
    if (i < BHn * MM * DD) {
        float s = 0.f;
#pragma unroll
        for (int seg = 0; seg < NSEG; seg++)
            s += g_ctxp[(size_t)seg * BHn * MM * DD + i];
        g_ctx[i] = s;
    }
    if (i < BHn * MM) {
        float s = 0.f;
#pragma unroll
        for (int seg = 0; seg < NSEG; seg++)
            s += g_ksump[(size_t)seg * BHn * MM + i];
        g_ksum[i] = s;
    }
}

// ---------------- fused query features + attention combine ----------------
// grid (BHn, 8), block 256. Each block: 512 rows (16 tiles of 32).
__global__ __launch_bounds__(256) void attn_fused(
    const float* __restrict__ Q, const float* __restrict__ proj)
{
    extern __shared__ float sm[];
    float* sPT  = sm;                 // [64][256]  64 KB
    float* sCtx = sPT + DD * MM;      // [256][64]  64 KB
    float* sQF  = sCtx + MM * DD;     // [32][256]  32 KB
    float* sX   = sQF + 32 * MM;      // [32][64]    8 KB
    float* sKs  = sX + 32 * DD;       // [256]
    float* sDp  = sKs + MM;           // [32]

    const int tid = threadIdx.x;
    const int bh  = blockIdx.x;
    const int b   = bh >> 4;
    const int h   = bh & 15;
    const int nblk = blockIdx.y * 512;
    const int lane = tid & 31;
    const int w    = tid >> 5;
    const int m0   = lane * 8;
    const int hl   = lane >> 4;       // row-in-pair
    const int dl   = lane & 15;       // d group (4 d)

    {
        const float4* pr = (const float4*)(proj + tid * DD);
#pragma unroll
        for (int t = 0; t < 16; t++) {
            float4 v = pr[t];
            int d = t * 4;
            sPT[(d + 0) * MM + tid] = v.x;
            sPT[(d + 1) * MM + tid] = v.y;
            sPT[(d + 2) * MM + tid] = v.z;
            sPT[(d + 3) * MM + tid] = v.w;
        }
        const float4* cb = (const float4*)(g_ctx + (size_t)bh * MM * DD);
        float4* sc4 = (float4*)sCtx;
#pragma unroll
        for (int t = 0; t < 16; t++) sc4[tid + t * 256] = cb[tid + t * 256];
        sKs[tid] = g_ksum[bh * MM + tid];
    }

    for (int it = 0; it < 16; it++) {
        const int n0 = nblk + it * 32;
        __syncthreads();
        {
            const float4* xr = (const float4*)(Q + ((size_t)bh * NSEQ + n0) * DD);
            float4* sx4 = (float4*)sX;
#pragma unroll
            for (int i = 0; i < 2; i++) {
                int f = tid * 2 + i;
                float4 v = xr[f];
                sx4[f] = make_float4(v.x * SCQ, v.y * SCQ, v.z * SCQ, v.w * SCQ);
            }
        }
        __syncthreads();

        // qf: dd + per-row max + exp + dp (4 rows per warp)
        {
            unsigned long long a2[4][4];
#pragma unroll
            for (int r = 0; r < 4; r++)
#pragma unroll
                for (int j = 0; j < 4; j++) a2[r][j] = 0ull;

#pragma unroll 8
            for (int d = 0; d < DD; d++) {
                const ulonglong2* bp = (const ulonglong2*)&sPT[d * MM + m0];
                ulonglong2 b01 = bp[0], b23 = bp[1];
#pragma unroll
                for (int r = 0; r < 4; r++) {
                    unsigned long long av = pack2(sX[(w * 4 + r) * DD + d]);
                    fma2(a2[r][0], av, b01.x); fma2(a2[r][1], av, b01.y);
                    fma2(a2[r][2], av, b23.x); fma2(a2[r][3], av, b23.y);
                }
            }
#pragma unroll
            for (int r = 0; r < 4; r++) {
                float v8[8];
#pragma unroll
                for (int j = 0; j < 4; j++) {
                    float2 f = unpack2(a2[r][j]);
                    v8[j * 2] = f.x; v8[j * 2 + 1] = f.y;
                }
                float mx = v8[0];
#pragma unroll
                for (int j = 1; j < 8; j++) mx = fmaxf(mx, v8[j]);
#pragma unroll
                for (int o = 16; o > 0; o >>= 1)
                    mx = fmaxf(mx, __shfl_xor_sync(0xffffffffu, mx, o));

                const float* xr = &sX[(w * 4 + r) * DD];
                float x0 = xr[lane * 2], x1 = xr[lane * 2 + 1];
                float p = x0 * x0 + x1 * x1;
#pragma unroll
                for (int o = 16; o > 0; o >>= 1) p += __shfl_xor_sync(0xffffffffu, p, o);
                float sub = 0.5f * p + mx;

                float o8[8];
                float dp = 0.f;
#pragma unroll
                for (int j = 0; j < 8; j++) {
                    o8[j] = RATIO * (__expf(v8[j] - sub) + EPSK);
                    dp += o8[j] * sKs[m0 + j];
                }
#pragma unroll
                for (int o = 16; o > 0; o >>= 1) dp += __shfl_xor_sync(0xffffffffu, dp, o);
                if (lane == 0) sDp[w * 4 + r] = dp;

                float4* dst = (float4*)&sQF[(w * 4 + r) * MM + m0];
                dst[0] = *(float4*)(o8);
                dst[1] = *(float4*)(o8 + 4);
            }
        }
        __syncwarp();

        // combine: warp handles its own rows w*4..w*4+3 (2 pairs, 4 d per lane)
        {
            const int rowA = w * 4 + hl;
            const int rowB = w * 4 + 2 + hl;
            const float* qA = &sQF[rowA * MM];
            const float* qB = &sQF[rowB * MM];
            unsigned long long aA0 = 0ull, aA1 = 0ull, aB0 = 0ull, aB1 = 0ull;
#pragma unroll 4
            for (int m = 0; m < MM; m++) {
                ulonglong2 cv = *(const ulonglong2*)&sCtx[m * DD + dl * 4];
                unsigned long long qa = pack2(qA[m]);
                unsigned long long qb = pack2(qB[m]);
                fma2(aA0, qa, cv.x); fma2(aA1, qa, cv.y);
                fma2(aB0, qb, cv.x); fma2(aB1, qb, cv.y);
            }
            float dA = 1.f / sDp[rowA];
            float dB = 1.f / sDp[rowB];
            float2 fA0 = unpack2(aA0), fA1 = unpack2(aA1);
            float2 fB0 = unpack2(aB0), fB1 = unpack2(aB1);
            size_t obase = ((size_t)(b * NSEQ + n0)) * EE + h * DD + dl * 4;
            *(float4*)(g_attn + obase + (size_t)rowA * EE) =
                make_float4(fA0.x * dA, fA0.y * dA, fA1.x * dA, fA1.y * dA);
            *(float4*)(g_attn + obase + (size_t)rowB * EE) =
                make_float4(fB0.x * dB, fB0.y * dB, fB1.x * dB, fB1.y * dB);
        }
    }
}

// ---------------- launch ----------------
extern "C" void kernel_launch(void* const* d_in, const int* in_sizes, int n_in,
                              void* d_out, int out_size) {
    const float* x    = (const float*)d_in[0];
    const float* Wq   = (const float*)d_in[1];
    const float* bq   = (const float*)d_in[2];
    const float* Wk   = (const float*)d_in[3];
    const float* bk   = (const float*)d_in[4];
    const float* Wv   = (const float*)d_in[5];
    const float* bv   = (const float*)d_in[6];
    const float* Wo   = (const float*)d_in[7];
    const float* bo   = (const float*)d_in[8];
    const float* proj = (const float*)d_in[9];
    float* out = (float*)d_out;

    float *pq, *pk, *pv, *pattn;
    __nv_bfloat16 *pah, *pal, *pwh, *pwl;
    cudaGetSymbolAddress((void**)&pq,    g_q);
    cudaGetSymbolAddress((void**)&pk,    g_k);
    cudaGetSymbolAddress((void**)&pv,    g_v);
    cudaGetSymbolAddress((void**)&pattn, g_attn);
    cudaGetSymbolAddress((void**)&pah,   g_ah);
    cudaGetSymbolAddress((void**)&pal,   g_al);
    cudaGetSymbolAddress((void**)&pwh,   g_wh);
    cudaGetSymbolAddress((void**)&pwl,   g_wl);

    const int KMAX_SMEM = (DD * MM + 32 * DD) * (int)sizeof(float);                      // 73728
    const int CTXF_SMEM = (DD * MM + 32 * MM + 32 * DD + 32 * DD) * (int)sizeof(float);  // 114688
    const int ATTN_SMEM = (DD * MM + MM * DD + 32 * MM + 32 * DD + MM + 32) * (int)sizeof(float); // 173184
    cudaFuncSetAttribute(kmax_kernel, cudaFuncAttributeMaxDynamicSharedMemorySize, KMAX_SMEM);
    cudaFuncSetAttribute(ctx_fused,   cudaFuncAttributeMaxDynamicSharedMemorySize, CTXF_SMEM);
    cudaFuncSetAttribute(attn_fused,  cudaFuncAttributeMaxDynamicSharedMemorySize, ATTN_SMEM);

    init_kernel<<<1, 32>>>();

    split_kernel<<<2048, 256>>>(x, pah, pal, TT * EE / 4);

    dim3 gg(EE / 128, TT / 128);

    split_kernel<<<512, 256>>>(Wq, pwh, pwl, EE * EE / 4);
    gemm_mma<1><<<gg, 256>>>(pah, pal, pwh, pwl, bq, pq);
    split_kernel<<<512, 256>>>(Wk, pwh, pwl, EE * EE / 4);
    gemm_mma<1><<<gg, 256>>>(pah, pal, pwh, pwl, bk, pk);
    split_kernel<<<512, 256>>>(Wv, pwh, pwl, EE * EE / 4);
    gemm_mma<1><<<gg, 256>>>(pah, pal, pwh, pwl, bv, pv);

    kmax_kernel<<<dim3(BHn, 16), 256, KMAX_SMEM>>>(pk, proj);

    ctx_fused<<<dim3(BHn, NSEG), 256, CTXF_SMEM>>>(pk, pv, proj);
    ctx_reduce_kernel<<<(BHn * MM * DD + 255) / 256, 256>>>();

    attn_fused<<<dim3(BHn, 8), 256, ATTN_SMEM>>>(pq, proj);

    split_kernel<<<2048, 256>>>(pattn, pah, pal, TT * EE / 4);
    split_kernel<<<512, 256>>>(Wo, pwh, pwl, EE * EE / 4);
    gemm_mma<0><<<gg, 256>>>(pah, pal, pwh, pwl, bo, out);
}